// round 12
// baseline (speedup 1.0000x reference)
#include <cuda_runtime.h>
#include <cstdint>

// Problem constants (fixed by the reference)
#define NN        64
#define INV_DX    63.0f
#define DXC       (1.0f/63.0f)
#define E_OUT_C   80.0f
#define FOUR_PI_F 12.566370614359172f
#define EPSF      1.1920928955078125e-07f
#define EPSF2     (EPSF*EPSF)
#define TPB       512
#define WPB       16                    // warps per block
#define WPP       2                     // points per warp (packed f32x2)
#define PPB       (WPB*WPP)             // 32 points per block
#define MAXQ2     512                   // staged (rounded-up) charge capacity

__device__ float    g_accum = 0.0f;
__device__ unsigned g_count = 0;

// ---- packed f32x2 helpers (FFMA2 path, sm_100+) ----
#define MUL2(d,a,b)    asm("mul.rn.f32x2 %0,%1,%2;"    : "=l"(d) : "l"(a), "l"(b))
#define ADD2(d,a,b)    asm("add.rn.f32x2 %0,%1,%2;"    : "=l"(d) : "l"(a), "l"(b))
#define FMA2(d,a,b,c)  asm("fma.rn.f32x2 %0,%1,%2,%3;" : "=l"(d) : "l"(a), "l"(b), "l"(c))
#define PK2(d,lo,hi)   asm("mov.b64 %0,{%1,%2};"       : "=l"(d) : "f"(lo), "f"(hi))
#define UPK2(lo,hi,s)  asm("mov.b64 {%0,%1},%2;"       : "=f"(lo), "=f"(hi) : "l"(s))

template<int NQC>   // NQC > 0: compile-time charge count; 0: runtime nq
__global__ __launch_bounds__(TPB)
void boundary_loss_fused(const float* __restrict__ outf,    // (2,1,64,64,64)
                         const float* __restrict__ q,      // (NQ)
                         const float* __restrict__ xq,     // (NQ,3)
                         const int*   __restrict__ xi,
                         const int*   __restrict__ yi,
                         const int*   __restrict__ zi,
                         const float* __restrict__ normals,// (NB,3)
                         float* __restrict__ outp,
                         int nb, int nq_rt)
{
    const int nq  = (NQC > 0) ? NQC : nq_rt;
    const int KIT = (NQC > 0) ? (NQC + 31) / 32
                              : (nq_rt + 31) / 32;
    const int nstage = KIT * 32;        // rounded-up staged count (<= MAXQ2)

    // pre-packed broadcast pairs: sA[j] = ({-x,-x},{-y,-y}), sB[j] = ({-z,-z},{q,q})
    __shared__ ulonglong2 sA[MAXQ2];
    __shared__ ulonglong2 sB[MAXQ2];

    int tid  = threadIdx.x;
    int wid  = tid >> 5;
    int lane = tid & 31;

    // ---- stage charges ONCE, packed; inert entries fill the round-up tail ----
    for (int j = tid; j < nstage && j < MAXQ2; j += TPB) {
        float vx, vy, vz, vq;
        if (j < nq) {
            vx = -xq[3*j + 0];
            vy = -xq[3*j + 1];
            vz = -xq[3*j + 2];
            vq =  q[j];
        } else {                         // inert: q=0 -> exact zero contribution
            vx = 1.0e9f; vy = 1.0e9f; vz = 1.0e9f; vq = 0.0f;
        }
        uint64_t xx, yy, zz, qq;
        PK2(xx, vx, vx);
        PK2(yy, vy, vy);
        PK2(zz, vz, vz);
        PK2(qq, vq, vq);
        sA[j] = make_ulonglong2(xx, yy);
        sB[j] = make_ulonglong2(zz, qq);
    }

    int gw = blockIdx.x * WPB + wid;
    int i0 = gw * WPP;
    int i1 = i0 + 1;
    bool a0 = (i0 < nb);
    bool a1 = (i1 < nb);
    int i0c = a0 ? i0 : 0;
    int i1c = a1 ? i1 : i0c;

    // ---- point descriptors, issued before the barrier ----
    int   x0 = xi[i0c], y0 = yi[i0c], z0 = zi[i0c];
    int   x1 = xi[i1c], y1 = yi[i1c], z1 = zi[i1c];
    float nx0 = normals[3*i0c], ny0 = normals[3*i0c+1], nz0 = normals[3*i0c+2];
    float nx1 = normals[3*i1c], ny1 = normals[3*i1c+1], nz1 = normals[3*i1c+2];

    // ---- stencil loads (broadcast), also pre-barrier ----
    const float* ob0 = outf;
    const float* ob1 = outf + (long)NN * NN * NN;
    long b0 = ((long)x0 * NN + y0) * NN + z0;
    long b1 = ((long)x1 * NN + y1) * NN + z1;
    float c0a = ob0[b0],       c0b = ob1[b0];
    float lfa = ob0[b0-NN*NN], lfb = ob1[b0-NN*NN];
    float rta = ob0[b0+NN*NN], rtb = ob1[b0+NN*NN];
    float bla = ob0[b0-NN],    blb = ob1[b0-NN];
    float aba = ob0[b0+NN],    abb = ob1[b0+NN];
    float bka = ob0[b0-1],     bkb = ob1[b0-1];
    float fra = ob0[b0+1],     frb = ob1[b0+1];
    float d0a = ob0[b1],       d0b = ob1[b1];
    float lga = ob0[b1-NN*NN], lgb = ob1[b1-NN*NN];
    float rua = ob0[b1+NN*NN], rub = ob1[b1+NN*NN];
    float bma = ob0[b1-NN],    bmb = ob1[b1-NN];
    float aca = ob0[b1+NN],    acb = ob1[b1+NN];
    float bja = ob0[b1-1],     bjb = ob1[b1-1];
    float fsa = ob0[b1+1],     fsb = ob1[b1+1];

    __syncthreads();

    // packed per-pair constants
    uint64_t PX, PY, PZ, NX2, NY2, NZ2, GS, GN;
    PK2(PX, x0 * DXC, x1 * DXC);
    PK2(PY, y0 * DXC, y1 * DXC);
    PK2(PZ, z0 * DXC, z1 * DXC);
    PK2(NX2, nx0, nx1);
    PK2(NY2, ny0, ny1);
    PK2(NZ2, nz0, nz1);
    PK2(GS, 0.0f, 0.0f);
    PK2(GN, 0.0f, 0.0f);

    // ---- packed charge loop: predicate-free, pre-packed operands ----
    #pragma unroll
    for (int k = 0; k < ((NQC > 0) ? (NQC + 31) / 32 : 0); k++) {
        int j = lane + 32 * k;
        ulonglong2 a = sA[j];           // {-x,-x}, {-y,-y}
        ulonglong2 b = sB[j];           // {-z,-z}, {q,q}

        uint64_t DX, DY, DZ, R2, RINV, QR, C, DOT;
        ADD2(DX, PX, a.x);
        ADD2(DY, PY, a.y);
        ADD2(DZ, PZ, b.x);
        MUL2(R2, DZ, DZ);
        FMA2(R2, DY, DY, R2);
        FMA2(R2, DX, DX, R2);

        float ra, rb;
        UPK2(ra, rb, R2);
        ra = fmaxf(ra, EPSF2);          // r==0 EPS semantics (grad term has dr=0)
        rb = fmaxf(rb, EPSF2);
        float ria = rsqrtf(ra);
        float rib = rsqrtf(rb);
        PK2(RINV, ria, rib);

        MUL2(QR, b.y, RINV);            // q / r
        ADD2(GS, GS, QR);
        MUL2(C, QR, RINV);
        MUL2(C, C, RINV);               // q / r^3
        MUL2(DOT, DZ, NZ2);
        FMA2(DOT, DY, NY2, DOT);
        FMA2(DOT, DX, NX2, DOT);
        FMA2(GN, C, DOT, GN);           // +c*dot; negate at end
    }

    // runtime-nq fallback (same math, dynamic trip count)
    if (NQC == 0) {
        for (int k = 0; k < KIT; k++) {
            int j = lane + 32 * k;
            ulonglong2 a = sA[j];
            ulonglong2 b = sB[j];
            uint64_t DX, DY, DZ, R2, RINV, QR, C, DOT;
            ADD2(DX, PX, a.x);
            ADD2(DY, PY, a.y);
            ADD2(DZ, PZ, b.x);
            MUL2(R2, DZ, DZ);
            FMA2(R2, DY, DY, R2);
            FMA2(R2, DX, DX, R2);
            float ra, rb;
            UPK2(ra, rb, R2);
            ra = fmaxf(ra, EPSF2);
            rb = fmaxf(rb, EPSF2);
            float ria = rsqrtf(ra);
            float rib = rsqrtf(rb);
            PK2(RINV, ria, rib);
            MUL2(QR, b.y, RINV);
            ADD2(GS, GS, QR);
            MUL2(C, QR, RINV);
            MUL2(C, C, RINV);
            MUL2(DOT, DZ, NZ2);
            FMA2(DOT, DY, NY2, DOT);
            FMA2(DOT, DX, NX2, DOT);
            FMA2(GN, C, DOT, GN);
        }
    }

    float gs0, gs1, gn0, gn1;
    UPK2(gs0, gs1, GS);
    UPK2(gn0, gn1, GN);

    // ---- warp butterfly reduction ----
    #pragma unroll
    for (int s = 16; s > 0; s >>= 1) {
        gs0 += __shfl_xor_sync(0xffffffffu, gs0, s);
        gs1 += __shfl_xor_sync(0xffffffffu, gs1, s);
        gn0 += __shfl_xor_sync(0xffffffffu, gn0, s);
        gn1 += __shfl_xor_sync(0xffffffffu, gn1, s);
    }

    const float inv4pi = 1.0f / FOUR_PI_F;
    float acc = 0.0f;

    if (a0) {
        float g = gs0 * inv4pi, gcnd = -gn0 * inv4pi;
        float gxin  = (nx0 > 0.0f) ? (c0a - lfa) : (rta - c0a);
        float gxout = (nx0 > 0.0f) ? (rta - c0a) : (c0a - lfa);
        float gyin  = (ny0 > 0.0f) ? (c0a - bla) : (aba - c0a);
        float gyout = (ny0 > 0.0f) ? (aba - c0a) : (c0a - bla);
        float gzin  = (nz0 > 0.0f) ? (c0a - bka) : (fra - c0a);
        float gzout = (nz0 > 0.0f) ? (fra - c0a) : (c0a - bka);
        float ndin  = (gxin *nx0 + gyin *ny0 + gzin *nz0) * INV_DX;
        float ndout = (gxout*nx0 + gyout*ny0 + gzout*nz0) * INV_DX;
        float tA = (ndin + gcnd) - E_OUT_C * ndout;
        gxin  = (nx0 > 0.0f) ? (c0b - lfb) : (rtb - c0b);
        gxout = (nx0 > 0.0f) ? (rtb - c0b) : (c0b - lfb);
        gyin  = (ny0 > 0.0f) ? (c0b - blb) : (abb - c0b);
        gyout = (ny0 > 0.0f) ? (abb - c0b) : (c0b - blb);
        gzin  = (nz0 > 0.0f) ? (c0b - bkb) : (frb - c0b);
        gzout = (nz0 > 0.0f) ? (frb - c0b) : (c0b - bkb);
        ndin  = (gxin *nx0 + gyin *ny0 + gzin *nz0) * INV_DX;
        ndout = (gxout*nx0 + gyout*ny0 + gzout*nz0) * INV_DX;
        float tB = (ndin + gcnd) - E_OUT_C * ndout;
        acc += g * g + 0.5f * (tA * tA + tB * tB);
    }
    if (a1) {
        float g = gs1 * inv4pi, gcnd = -gn1 * inv4pi;
        float gxin  = (nx1 > 0.0f) ? (d0a - lga) : (rua - d0a);
        float gxout = (nx1 > 0.0f) ? (rua - d0a) : (d0a - lga);
        float gyin  = (ny1 > 0.0f) ? (d0a - bma) : (aca - d0a);
        float gyout = (ny1 > 0.0f) ? (aca - d0a) : (d0a - bma);
        float gzin  = (nz1 > 0.0f) ? (d0a - bja) : (fsa - d0a);
        float gzout = (nz1 > 0.0f) ? (fsa - d0a) : (d0a - bja);
        float ndin  = (gxin *nx1 + gyin *ny1 + gzin *nz1) * INV_DX;
        float ndout = (gxout*nx1 + gyout*ny1 + gzout*nz1) * INV_DX;
        float tA = (ndin + gcnd) - E_OUT_C * ndout;
        gxin  = (nx1 > 0.0f) ? (d0b - lgb) : (rub - d0b);
        gxout = (nx1 > 0.0f) ? (rub - d0b) : (d0b - lgb);
        gyin  = (ny1 > 0.0f) ? (d0b - bmb) : (acb - d0b);
        gyout = (ny1 > 0.0f) ? (acb - d0b) : (d0b - bmb);
        gzin  = (nz1 > 0.0f) ? (d0b - bjb) : (fsb - d0b);
        gzout = (nz1 > 0.0f) ? (fsb - d0b) : (d0b - bjb);
        ndin  = (gxin *nx1 + gyin *ny1 + gzin *nz1) * INV_DX;
        ndout = (gxout*nx1 + gyout*ny1 + gzout*nz1) * INV_DX;
        float tB = (ndin + gcnd) - E_OUT_C * ndout;
        acc += g * g + 0.5f * (tA * tA + tB * tB);
    }

    // ---- per-warp no-return RED into global accumulator, then block election ----
    if (lane == 0) {
        atomicAdd(&g_accum, acc);       // return unused -> REDG
    }
    __syncthreads();                    // all warps' REDs issued
    if (tid == 0) {
        __threadfence();                // order REDs before count
        unsigned old = atomicAdd(&g_count, 1u);
        if (old == gridDim.x - 1) {     // last block: finalize + reset
            float total = *(volatile float*)&g_accum;
            outp[0] = total / (float)nb;
            g_accum = 0.0f;
            __threadfence();
            g_count = 0;
        }
    }
}

extern "C" void kernel_launch(void* const* d_in, const int* in_sizes, int n_in,
                              void* d_out, int out_size)
{
    // metadata order: output, q, xq, points, x_idx, y_idx, z_idx, normals
    const float* outf    = (const float*)d_in[0];
    const float* q       = (const float*)d_in[1];
    const float* xq      = (const float*)d_in[2];
    const int*   xi      = (const int*)  d_in[4];
    const int*   yi      = (const int*)  d_in[5];
    const int*   zi      = (const int*)  d_in[6];
    const float* normals = (const float*)d_in[7];

    int nq = in_sizes[1];
    int nb = in_sizes[4];

    int blocks = (nb + PPB - 1) / PPB;

    if (nq == 200) {
        boundary_loss_fused<200><<<blocks, TPB>>>(outf, q, xq, xi, yi, zi, normals,
                                                  (float*)d_out, nb, nq);
    } else {
        boundary_loss_fused<0><<<blocks, TPB>>>(outf, q, xq, xi, yi, zi, normals,
                                                (float*)d_out, nb, nq);
    }
}

// round 14
// speedup vs baseline: 1.3015x; 1.3015x over previous
#include <cuda_runtime.h>
#include <cstdint>

// Problem constants (fixed by the reference)
#define NN        64
#define INV_DX    63.0f
#define DXC       (1.0f/63.0f)
#define E_OUT_C   80.0f
#define FOUR_PI_F 12.566370614359172f
#define EPSF      1.1920928955078125e-07f
#define EPSF2     (EPSF*EPSF)
#define TPB       512
#define WPB       16                    // warps per block
#define WPP       2                     // points per warp (packed f32x2)
#define PPB       (WPB*WPP)             // 32 points per block
#define MAXQ      512                   // staged charge capacity (rounded up)

__device__ float    g_accum = 0.0f;
__device__ unsigned g_count = 0;

// ---- packed f32x2 helpers (FFMA2 path, sm_100+) ----
#define MUL2(d,a,b)    asm("mul.rn.f32x2 %0,%1,%2;"    : "=l"(d) : "l"(a), "l"(b))
#define ADD2(d,a,b)    asm("add.rn.f32x2 %0,%1,%2;"    : "=l"(d) : "l"(a), "l"(b))
#define FMA2(d,a,b,c)  asm("fma.rn.f32x2 %0,%1,%2,%3;" : "=l"(d) : "l"(a), "l"(b), "l"(c))
#define PK2(d,lo,hi)   asm("mov.b64 %0,{%1,%2};"       : "=l"(d) : "f"(lo), "f"(hi))
#define UPK2(lo,hi,s)  asm("mov.b64 {%0,%1},%2;"       : "=f"(lo), "=f"(hi) : "l"(s))

template<int NQC>   // NQC > 0: compile-time charge count; 0: runtime nq
__global__ __launch_bounds__(TPB)
void boundary_loss_fused(const float* __restrict__ outf,    // (2,1,64,64,64)
                         const float* __restrict__ q,      // (NQ)
                         const float* __restrict__ xq,     // (NQ,3)
                         const int*   __restrict__ xi,
                         const int*   __restrict__ yi,
                         const int*   __restrict__ zi,
                         const float* __restrict__ normals,// (NB,3)
                         float* __restrict__ outp,
                         int nb, int nq_rt)
{
    const int nq  = (NQC > 0) ? NQC : nq_rt;
    const int KIT = (NQC > 0) ? (NQC + 31) / 32 : (nq_rt + 31) / 32;
    const int nstage = KIT * 32;        // rounded-up staged count

    __shared__ float4 s4[MAXQ];         // {-x, -y, -z, q} per charge (+ inert tail)
    __shared__ float  warp_acc[WPB];

    int tid  = threadIdx.x;
    int wid  = tid >> 5;
    int lane = tid & 31;

    // stage charges; tail entries are inert (q=0 -> exact zero contribution)
    for (int j = tid; j < nstage && j < MAXQ; j += TPB) {
        float4 v;
        if (j < nq) {
            v.x = -xq[3*j + 0];
            v.y = -xq[3*j + 1];
            v.z = -xq[3*j + 2];
            v.w =  q[j];
        } else {
            v.x = 1.0e9f; v.y = 1.0e9f; v.z = 1.0e9f; v.w = 0.0f;
        }
        s4[j] = v;
    }

    int gw = blockIdx.x * WPB + wid;
    int i0 = gw * WPP;
    int i1 = i0 + 1;
    bool a0 = (i0 < nb);
    bool a1 = (i1 < nb);
    int i0c = a0 ? i0 : 0;
    int i1c = a1 ? i1 : i0c;

    // ---- point descriptors, issued before the barrier ----
    int   x0 = xi[i0c], y0 = yi[i0c], z0 = zi[i0c];
    int   x1 = xi[i1c], y1 = yi[i1c], z1 = zi[i1c];
    float nx0 = normals[3*i0c], ny0 = normals[3*i0c+1], nz0 = normals[3*i0c+2];
    float nx1 = normals[3*i1c], ny1 = normals[3*i1c+1], nz1 = normals[3*i1c+2];

    // ---- stencil loads (broadcast), also pre-barrier ----
    const float* ob0 = outf;
    const float* ob1 = outf + (long)NN * NN * NN;
    long b0 = ((long)x0 * NN + y0) * NN + z0;
    long b1 = ((long)x1 * NN + y1) * NN + z1;
    float c0a = ob0[b0],       c0b = ob1[b0];
    float lfa = ob0[b0-NN*NN], lfb = ob1[b0-NN*NN];
    float rta = ob0[b0+NN*NN], rtb = ob1[b0+NN*NN];
    float bla = ob0[b0-NN],    blb = ob1[b0-NN];
    float aba = ob0[b0+NN],    abb = ob1[b0+NN];
    float bka = ob0[b0-1],     bkb = ob1[b0-1];
    float fra = ob0[b0+1],     frb = ob1[b0+1];
    float d0a = ob0[b1],       d0b = ob1[b1];
    float lga = ob0[b1-NN*NN], lgb = ob1[b1-NN*NN];
    float rua = ob0[b1+NN*NN], rub = ob1[b1+NN*NN];
    float bma = ob0[b1-NN],    bmb = ob1[b1-NN];
    float aca = ob0[b1+NN],    acb = ob1[b1+NN];
    float bja = ob0[b1-1],     bjb = ob1[b1-1];
    float fsa = ob0[b1+1],     fsb = ob1[b1+1];

    __syncthreads();

    // packed per-pair constants
    uint64_t PX, PY, PZ, NX2, NY2, NZ2, GS, GN;
    PK2(PX, x0 * DXC, x1 * DXC);
    PK2(PY, y0 * DXC, y1 * DXC);
    PK2(PZ, z0 * DXC, z1 * DXC);
    PK2(NX2, nx0, nx1);
    PK2(NY2, ny0, ny1);
    PK2(NZ2, nz0, nz1);
    PK2(GS, 0.0f, 0.0f);
    PK2(GN, 0.0f, 0.0f);

    // ---- packed charge loop: predicate-free (inert tail), 2 points / f32x2 op ----
    const int KCONST = (NQC > 0) ? (NQC + 31) / 32 : 0;
    #pragma unroll
    for (int k = 0; k < KCONST; k++) {
        int j = lane + 32 * k;
        float4 v = s4[j];

        uint64_t NCX, NCY, NCZ, QQ;
        PK2(NCX, v.x, v.x);
        PK2(NCY, v.y, v.y);
        PK2(NCZ, v.z, v.z);
        PK2(QQ,  v.w, v.w);

        uint64_t DX, DY, DZ, R2, RINV, QR, C, DOT;
        ADD2(DX, PX, NCX);
        ADD2(DY, PY, NCY);
        ADD2(DZ, PZ, NCZ);
        MUL2(R2, DZ, DZ);
        FMA2(R2, DY, DY, R2);
        FMA2(R2, DX, DX, R2);

        float ra, rb;
        UPK2(ra, rb, R2);
        ra = fmaxf(ra, EPSF2);          // r==0 EPS semantics (grad term has dr=0)
        rb = fmaxf(rb, EPSF2);
        float ria = rsqrtf(ra);
        float rib = rsqrtf(rb);
        PK2(RINV, ria, rib);

        MUL2(QR, QQ, RINV);             // q / r
        ADD2(GS, GS, QR);
        MUL2(C, QR, RINV);
        MUL2(C, C, RINV);               // q / r^3
        MUL2(DOT, DZ, NZ2);
        FMA2(DOT, DY, NY2, DOT);
        FMA2(DOT, DX, NX2, DOT);
        FMA2(GN, C, DOT, GN);           // +c*dot; negated at the end
    }

    // runtime-nq fallback (same math, dynamic trip count)
    if (NQC == 0) {
        for (int k = 0; k < KIT; k++) {
            int j = lane + 32 * k;
            float4 v = s4[j];
            uint64_t NCX, NCY, NCZ, QQ;
            PK2(NCX, v.x, v.x);
            PK2(NCY, v.y, v.y);
            PK2(NCZ, v.z, v.z);
            PK2(QQ,  v.w, v.w);
            uint64_t DX, DY, DZ, R2, RINV, QR, C, DOT;
            ADD2(DX, PX, NCX);
            ADD2(DY, PY, NCY);
            ADD2(DZ, PZ, NCZ);
            MUL2(R2, DZ, DZ);
            FMA2(R2, DY, DY, R2);
            FMA2(R2, DX, DX, R2);
            float ra, rb;
            UPK2(ra, rb, R2);
            ra = fmaxf(ra, EPSF2);
            rb = fmaxf(rb, EPSF2);
            float ria = rsqrtf(ra);
            float rib = rsqrtf(rb);
            PK2(RINV, ria, rib);
            MUL2(QR, QQ, RINV);
            ADD2(GS, GS, QR);
            MUL2(C, QR, RINV);
            MUL2(C, C, RINV);
            MUL2(DOT, DZ, NZ2);
            FMA2(DOT, DY, NY2, DOT);
            FMA2(DOT, DX, NX2, DOT);
            FMA2(GN, C, DOT, GN);
        }
    }

    float gs0, gs1, gn0, gn1;
    UPK2(gs0, gs1, GS);
    UPK2(gn0, gn1, GN);

    // ---- warp butterfly reduction (4 chains interleaved) ----
    #pragma unroll
    for (int s = 16; s > 0; s >>= 1) {
        gs0 += __shfl_xor_sync(0xffffffffu, gs0, s);
        gs1 += __shfl_xor_sync(0xffffffffu, gs1, s);
        gn0 += __shfl_xor_sync(0xffffffffu, gn0, s);
        gn1 += __shfl_xor_sync(0xffffffffu, gn1, s);
    }

    const float inv4pi = 1.0f / FOUR_PI_F;
    float acc = 0.0f;

    if (a0) {
        float g = gs0 * inv4pi, gcnd = -gn0 * inv4pi;
        float gxin  = (nx0 > 0.0f) ? (c0a - lfa) : (rta - c0a);
        float gxout = (nx0 > 0.0f) ? (rta - c0a) : (c0a - lfa);
        float gyin  = (ny0 > 0.0f) ? (c0a - bla) : (aba - c0a);
        float gyout = (ny0 > 0.0f) ? (aba - c0a) : (c0a - bla);
        float gzin  = (nz0 > 0.0f) ? (c0a - bka) : (fra - c0a);
        float gzout = (nz0 > 0.0f) ? (fra - c0a) : (c0a - bka);
        float ndin  = (gxin *nx0 + gyin *ny0 + gzin *nz0) * INV_DX;
        float ndout = (gxout*nx0 + gyout*ny0 + gzout*nz0) * INV_DX;
        float tA = (ndin + gcnd) - E_OUT_C * ndout;
        gxin  = (nx0 > 0.0f) ? (c0b - lfb) : (rtb - c0b);
        gxout = (nx0 > 0.0f) ? (rtb - c0b) : (c0b - lfb);
        gyin  = (ny0 > 0.0f) ? (c0b - blb) : (abb - c0b);
        gyout = (ny0 > 0.0f) ? (abb - c0b) : (c0b - blb);
        gzin  = (nz0 > 0.0f) ? (c0b - bkb) : (frb - c0b);
        gzout = (nz0 > 0.0f) ? (frb - c0b) : (c0b - bkb);
        ndin  = (gxin *nx0 + gyin *ny0 + gzin *nz0) * INV_DX;
        ndout = (gxout*nx0 + gyout*ny0 + gzout*nz0) * INV_DX;
        float tB = (ndin + gcnd) - E_OUT_C * ndout;
        acc += g * g + 0.5f * (tA * tA + tB * tB);
    }
    if (a1) {
        float g = gs1 * inv4pi, gcnd = -gn1 * inv4pi;
        float gxin  = (nx1 > 0.0f) ? (d0a - lga) : (rua - d0a);
        float gxout = (nx1 > 0.0f) ? (rua - d0a) : (d0a - lga);
        float gyin  = (ny1 > 0.0f) ? (d0a - bma) : (aca - d0a);
        float gyout = (ny1 > 0.0f) ? (aca - d0a) : (d0a - bma);
        float gzin  = (nz1 > 0.0f) ? (d0a - bja) : (fsa - d0a);
        float gzout = (nz1 > 0.0f) ? (fsa - d0a) : (d0a - bja);
        float ndin  = (gxin *nx1 + gyin *ny1 + gzin *nz1) * INV_DX;
        float ndout = (gxout*nx1 + gyout*ny1 + gzout*nz1) * INV_DX;
        float tA = (ndin + gcnd) - E_OUT_C * ndout;
        gxin  = (nx1 > 0.0f) ? (d0b - lgb) : (rub - d0b);
        gxout = (nx1 > 0.0f) ? (rub - d0b) : (d0b - lgb);
        gyin  = (ny1 > 0.0f) ? (d0b - bmb) : (acb - d0b);
        gyout = (ny1 > 0.0f) ? (acb - d0b) : (d0b - bmb);
        gzin  = (nz1 > 0.0f) ? (d0b - bjb) : (fsb - d0b);
        gzout = (nz1 > 0.0f) ? (fsb - d0b) : (d0b - bjb);
        ndin  = (gxin *nx1 + gyin *ny1 + gzin *nz1) * INV_DX;
        ndout = (gxout*nx1 + gyout*ny1 + gzout*nz1) * INV_DX;
        float tB = (ndin + gcnd) - E_OUT_C * ndout;
        acc += g * g + 0.5f * (tA * tA + tB * tB);
    }

    // ---- block reduction: one value per warp, ONE global atomic per block ----
    if (lane == 0) warp_acc[wid] = acc;
    __syncthreads();

    if (tid == 0) {
        float bsum = 0.0f;
        #pragma unroll
        for (int w = 0; w < WPB; w++) bsum += warp_acc[w];
        atomicAdd(&g_accum, bsum);
        __threadfence();
        unsigned old = atomicAdd(&g_count, 1u);
        if (old == gridDim.x - 1) {     // last block: finalize + reset
            float total = *(volatile float*)&g_accum;
            outp[0] = total / (float)nb;
            g_accum = 0.0f;
            __threadfence();
            g_count = 0;
        }
    }
}

extern "C" void kernel_launch(void* const* d_in, const int* in_sizes, int n_in,
                              void* d_out, int out_size)
{
    // metadata order: output, q, xq, points, x_idx, y_idx, z_idx, normals
    const float* outf    = (const float*)d_in[0];
    const float* q       = (const float*)d_in[1];
    const float* xq      = (const float*)d_in[2];
    const int*   xi      = (const int*)  d_in[4];
    const int*   yi      = (const int*)  d_in[5];
    const int*   zi      = (const int*)  d_in[6];
    const float* normals = (const float*)d_in[7];

    int nq = in_sizes[1];
    int nb = in_sizes[4];

    int blocks = (nb + PPB - 1) / PPB;

    if (nq == 200) {
        boundary_loss_fused<200><<<blocks, TPB>>>(outf, q, xq, xi, yi, zi, normals,
                                                  (float*)d_out, nb, nq);
    } else {
        boundary_loss_fused<0><<<blocks, TPB>>>(outf, q, xq, xi, yi, zi, normals,
                                                (float*)d_out, nb, nq);
    }
}

// round 15
// speedup vs baseline: 1.3111x; 1.0074x over previous
#include <cuda_runtime.h>
#include <cstdint>

// Problem constants (fixed by the reference)
#define NN        64
#define INV_DX    63.0f
#define DXC       (1.0f/63.0f)
#define FOUR_PI_F 12.566370614359172f
#define EPSF      1.1920928955078125e-07f
#define EPSF2     (EPSF*EPSF)
#define TPB       512
#define WPB       16                    // warps per block
#define WPP       2                     // points per warp (packed f32x2)
#define PPB       (WPB*WPP)             // 32 points per block
#define MAXQ      512                   // staged charge capacity (rounded up)

// (1-E_OUT)/2 = -39.5 ; (1+E_OUT)/2 = 40.5  (E_IN = 1, E_OUT = 80)
#define CM  (-39.5f * INV_DX)
#define CP  ( 40.5f * INV_DX)

__device__ float    g_accum = 0.0f;
__device__ unsigned g_count = 0;

// ---- packed f32x2 helpers (FFMA2 path, sm_100+) ----
#define MUL2(d,a,b)    asm("mul.rn.f32x2 %0,%1,%2;"    : "=l"(d) : "l"(a), "l"(b))
#define ADD2(d,a,b)    asm("add.rn.f32x2 %0,%1,%2;"    : "=l"(d) : "l"(a), "l"(b))
#define FMA2(d,a,b,c)  asm("fma.rn.f32x2 %0,%1,%2,%3;" : "=l"(d) : "l"(a), "l"(b), "l"(c))
#define PK2(d,lo,hi)   asm("mov.b64 %0,{%1,%2};"       : "=l"(d) : "f"(lo), "f"(hi))
#define UPK2(lo,hi,s)  asm("mov.b64 {%0,%1},%2;"       : "=f"(lo), "=f"(hi) : "l"(s))

template<int NQC>   // NQC > 0: compile-time charge count; 0: runtime nq
__global__ __launch_bounds__(TPB)
void boundary_loss_fused(const float* __restrict__ outf,    // (2,1,64,64,64)
                         const float* __restrict__ q,      // (NQ)
                         const float* __restrict__ xq,     // (NQ,3)
                         const int*   __restrict__ xi,
                         const int*   __restrict__ yi,
                         const int*   __restrict__ zi,
                         const float* __restrict__ normals,// (NB,3)
                         float* __restrict__ outp,
                         int nb, int nq_rt)
{
    const int nq  = (NQC > 0) ? NQC : nq_rt;
    const int KIT = (NQC > 0) ? (NQC + 31) / 32 : (nq_rt + 31) / 32;
    const int nstage = KIT * 32;        // rounded-up staged count

    __shared__ float4 s4[MAXQ];         // {-x, -y, -z, q} per charge (+ inert tail)
    __shared__ float  warp_acc[WPB];

    int tid  = threadIdx.x;
    int wid  = tid >> 5;
    int lane = tid & 31;

    // stage charges; tail entries are inert (q=0 -> exact zero contribution)
    for (int j = tid; j < nstage && j < MAXQ; j += TPB) {
        float4 v;
        if (j < nq) {
            v.x = -xq[3*j + 0];
            v.y = -xq[3*j + 1];
            v.z = -xq[3*j + 2];
            v.w =  q[j];
        } else {
            v.x = 1.0e9f; v.y = 1.0e9f; v.z = 1.0e9f; v.w = 0.0f;
        }
        s4[j] = v;
    }

    int gw = blockIdx.x * WPB + wid;
    int i0 = gw * WPP;
    int i1 = i0 + 1;
    bool a0 = (i0 < nb);
    bool a1 = (i1 < nb);
    int i0c = a0 ? i0 : 0;
    int i1c = a1 ? i1 : i0c;

    // ---- point descriptors, issued before the barrier ----
    int   x0 = xi[i0c], y0 = yi[i0c], z0 = zi[i0c];
    int   x1 = xi[i1c], y1 = yi[i1c], z1 = zi[i1c];
    float nx0 = normals[3*i0c], ny0 = normals[3*i0c+1], nz0 = normals[3*i0c+2];
    float nx1 = normals[3*i1c], ny1 = normals[3*i1c+1], nz1 = normals[3*i1c+2];

    // ---- stencil loads (broadcast), also pre-barrier ----
    const float* ob0 = outf;
    const float* ob1 = outf + (long)NN * NN * NN;
    long b0 = ((long)x0 * NN + y0) * NN + z0;
    long b1 = ((long)x1 * NN + y1) * NN + z1;
    float c0a = ob0[b0],       c0b = ob1[b0];
    float lfa = ob0[b0-NN*NN], lfb = ob1[b0-NN*NN];
    float rta = ob0[b0+NN*NN], rtb = ob1[b0+NN*NN];
    float bla = ob0[b0-NN],    blb = ob1[b0-NN];
    float aba = ob0[b0+NN],    abb = ob1[b0+NN];
    float bka = ob0[b0-1],     bkb = ob1[b0-1];
    float fra = ob0[b0+1],     frb = ob1[b0+1];
    float d0a = ob0[b1],       d0b = ob1[b1];
    float lga = ob0[b1-NN*NN], lgb = ob1[b1-NN*NN];
    float rua = ob0[b1+NN*NN], rub = ob1[b1+NN*NN];
    float bma = ob0[b1-NN],    bmb = ob1[b1-NN];
    float aca = ob0[b1+NN],    acb = ob1[b1+NN];
    float bja = ob0[b1-1],     bjb = ob1[b1-1];
    float fsa = ob0[b1+1],     fsb = ob1[b1+1];

    __syncthreads();

    // packed per-pair constants
    uint64_t PX, PY, PZ, NX2, NY2, NZ2, GS, GN;
    PK2(PX, x0 * DXC, x1 * DXC);
    PK2(PY, y0 * DXC, y1 * DXC);
    PK2(PZ, z0 * DXC, z1 * DXC);
    PK2(NX2, nx0, nx1);
    PK2(NY2, ny0, ny1);
    PK2(NZ2, nz0, nz1);
    PK2(GS, 0.0f, 0.0f);
    PK2(GN, 0.0f, 0.0f);

    // ---- packed charge loop: predicate-free (inert tail), 2 points / f32x2 op ----
    const int KCONST = (NQC > 0) ? (NQC + 31) / 32 : 0;
    #pragma unroll
    for (int k = 0; k < KCONST; k++) {
        int j = lane + 32 * k;
        float4 v = s4[j];

        uint64_t NCX, NCY, NCZ, QQ;
        PK2(NCX, v.x, v.x);
        PK2(NCY, v.y, v.y);
        PK2(NCZ, v.z, v.z);
        PK2(QQ,  v.w, v.w);

        uint64_t DX, DY, DZ, R2, RINV, QR, C, DOT;
        ADD2(DX, PX, NCX);
        ADD2(DY, PY, NCY);
        ADD2(DZ, PZ, NCZ);
        MUL2(R2, DZ, DZ);
        FMA2(R2, DY, DY, R2);
        FMA2(R2, DX, DX, R2);

        float ra, rb;
        UPK2(ra, rb, R2);
        ra = fmaxf(ra, EPSF2);          // r==0 EPS semantics (grad term has dr=0)
        rb = fmaxf(rb, EPSF2);
        float ria = rsqrtf(ra);
        float rib = rsqrtf(rb);
        PK2(RINV, ria, rib);

        MUL2(QR, QQ, RINV);             // q / r
        ADD2(GS, GS, QR);
        MUL2(C, QR, RINV);
        MUL2(C, C, RINV);               // q / r^3
        MUL2(DOT, DZ, NZ2);
        FMA2(DOT, DY, NY2, DOT);
        FMA2(DOT, DX, NX2, DOT);
        FMA2(GN, C, DOT, GN);           // +c*dot; negated at the end
    }

    // runtime-nq fallback (same math, dynamic trip count)
    if (NQC == 0) {
        for (int k = 0; k < KIT; k++) {
            int j = lane + 32 * k;
            float4 v = s4[j];
            uint64_t NCX, NCY, NCZ, QQ;
            PK2(NCX, v.x, v.x);
            PK2(NCY, v.y, v.y);
            PK2(NCZ, v.z, v.z);
            PK2(QQ,  v.w, v.w);
            uint64_t DX, DY, DZ, R2, RINV, QR, C, DOT;
            ADD2(DX, PX, NCX);
            ADD2(DY, PY, NCY);
            ADD2(DZ, PZ, NCZ);
            MUL2(R2, DZ, DZ);
            FMA2(R2, DY, DY, R2);
            FMA2(R2, DX, DX, R2);
            float ra, rb;
            UPK2(ra, rb, R2);
            ra = fmaxf(ra, EPSF2);
            rb = fmaxf(rb, EPSF2);
            float ria = rsqrtf(ra);
            float rib = rsqrtf(rb);
            PK2(RINV, ria, rib);
            MUL2(QR, QQ, RINV);
            ADD2(GS, GS, QR);
            MUL2(C, QR, RINV);
            MUL2(C, C, RINV);
            MUL2(DOT, DZ, NZ2);
            FMA2(DOT, DY, NY2, DOT);
            FMA2(DOT, DX, NX2, DOT);
            FMA2(GN, C, DOT, GN);
        }
    }

    float gs0, gs1, gn0, gn1;
    UPK2(gs0, gs1, GS);
    UPK2(gn0, gn1, GN);

    // ---- warp butterfly reduction (4 chains interleaved) ----
    #pragma unroll
    for (int s = 16; s > 0; s >>= 1) {
        gs0 += __shfl_xor_sync(0xffffffffu, gs0, s);
        gs1 += __shfl_xor_sync(0xffffffffu, gs1, s);
        gn0 += __shfl_xor_sync(0xffffffffu, gn0, s);
        gn1 += __shfl_xor_sync(0xffffffffu, gn1, s);
    }

    const float inv4pi = 1.0f / FOUR_PI_F;
    float acc = 0.0f;

    // Branchless stencil epilogue:
    //   t = sum_d [ CM*n_d*(r-l)_d + CP*|n_d|*(2c-l-r)_d ] + gcnd
    // (exactly equivalent to the in/out select form; n_d==0 edge: both terms 0)
    if (a0) {
        float g = gs0 * inv4pi, gcnd = -gn0 * inv4pi;
        float ux = CM * nx0, uy = CM * ny0, uz = CM * nz0;
        float wx = CP * fabsf(nx0), wy = CP * fabsf(ny0), wz = CP * fabsf(nz0);
        float tA = gcnd
                 + ux * (rta - lfa) + wx * (2.0f*c0a - lfa - rta)
                 + uy * (aba - bla) + wy * (2.0f*c0a - bla - aba)
                 + uz * (fra - bka) + wz * (2.0f*c0a - bka - fra);
        float tB = gcnd
                 + ux * (rtb - lfb) + wx * (2.0f*c0b - lfb - rtb)
                 + uy * (abb - blb) + wy * (2.0f*c0b - blb - abb)
                 + uz * (frb - bkb) + wz * (2.0f*c0b - bkb - frb);
        acc += g * g + 0.5f * (tA * tA + tB * tB);
    }
    if (a1) {
        float g = gs1 * inv4pi, gcnd = -gn1 * inv4pi;
        float ux = CM * nx1, uy = CM * ny1, uz = CM * nz1;
        float wx = CP * fabsf(nx1), wy = CP * fabsf(ny1), wz = CP * fabsf(nz1);
        float tA = gcnd
                 + ux * (rua - lga) + wx * (2.0f*d0a - lga - rua)
                 + uy * (aca - bma) + wy * (2.0f*d0a - bma - aca)
                 + uz * (fsa - bja) + wz * (2.0f*d0a - bja - fsa);
        float tB = gcnd
                 + ux * (rub - lgb) + wx * (2.0f*d0b - lgb - rub)
                 + uy * (acb - bmb) + wy * (2.0f*d0b - bmb - acb)
                 + uz * (fsb - bjb) + wz * (2.0f*d0b - bjb - fsb);
        acc += g * g + 0.5f * (tA * tA + tB * tB);
    }

    // ---- block reduction: one value per warp, ONE global atomic per block ----
    if (lane == 0) warp_acc[wid] = acc;
    __syncthreads();

    if (tid == 0) {
        float bsum = 0.0f;
        #pragma unroll
        for (int w = 0; w < WPB; w++) bsum += warp_acc[w];
        atomicAdd(&g_accum, bsum);
        __threadfence();
        unsigned old = atomicAdd(&g_count, 1u);
        if (old == gridDim.x - 1) {     // last block: finalize + reset
            float total = *(volatile float*)&g_accum;
            outp[0] = total / (float)nb;
            g_accum = 0.0f;
            __threadfence();
            g_count = 0;
        }
    }
}

extern "C" void kernel_launch(void* const* d_in, const int* in_sizes, int n_in,
                              void* d_out, int out_size)
{
    // metadata order: output, q, xq, points, x_idx, y_idx, z_idx, normals
    const float* outf    = (const float*)d_in[0];
    const float* q       = (const float*)d_in[1];
    const float* xq      = (const float*)d_in[2];
    const int*   xi      = (const int*)  d_in[4];
    const int*   yi      = (const int*)  d_in[5];
    const int*   zi      = (const int*)  d_in[6];
    const float* normals = (const float*)d_in[7];

    int nq = in_sizes[1];
    int nb = in_sizes[4];

    int blocks = (nb + PPB - 1) / PPB;

    if (nq == 200) {
        boundary_loss_fused<200><<<blocks, TPB>>>(outf, q, xq, xi, yi, zi, normals,
                                                  (float*)d_out, nb, nq);
    } else {
        boundary_loss_fused<0><<<blocks, TPB>>>(outf, q, xq, xi, yi, zi, normals,
                                                (float*)d_out, nb, nq);
    }
}